// round 1
// baseline (speedup 1.0000x reference)
#include <cuda_runtime.h>
#include <math.h>

#define Bsz  64
#define Cc   3
#define Hh   512
#define Ww   512
#define Pp   16
#define Dd   256
#define NPp  1024
#define NTOK 1025
#define HIDN 1024
#define NL   6
#define NCls 1000
#define ROWS (Bsz*NTOK)       /* 65600 */
#define KIN  768              /* C*P*P */
#define EPSV 1e-5f

/* ------------------------ scratch (device globals; no cudaMalloc allowed) */
__device__ float g_t   [Bsz*NTOK*Dd];
__device__ float g_h   [Bsz*NTOK*Dd];
__device__ float g_tmp1[Bsz*NTOK*Dd];
__device__ float g_tmp2[Bsz*NTOK*Dd];
__device__ float g_hid [Bsz*NTOK*HIDN];
__device__ float g_col [Bsz*NPp*KIN];
__device__ float g_wmat[KIN*Dd];
__device__ float g_CM  [NTOK*NTOK];
__device__ float g_SM  [NTOK*NTOK];
__device__ float g_CN  [Dd*Dd];
__device__ float g_SN  [Dd*Dd];
__device__ float g_pool[Bsz*Dd];

/* ------------------------ generic tiled SGEMM: C = beta*C + act(alpha*A@B + bias)
   row-major, batched via strides (stride may be 0 to broadcast). 128x128x16 tile,
   256 threads, 8x8 microtile, float4 smem fragment loads. */
template<int ACT>
__global__ __launch_bounds__(256)
void sgemm(const float* __restrict__ A, const float* __restrict__ B,
           float* __restrict__ C, int M, int N, int K,
           long long sA, long long sB, long long sC,
           float alpha, int beta, const float* __restrict__ bias)
{
    __shared__ float As[16][132];   /* [k][m], padded so float4 rows stay 16B aligned */
    __shared__ float Bs[16][128];   /* [k][n] */

    const int bz = blockIdx.z;
    A += (long long)bz * sA;
    B += (long long)bz * sB;
    C += (long long)bz * sC;

    const int m0 = blockIdx.y * 128;
    const int n0 = blockIdx.x * 128;
    const int tid = threadIdx.x;
    const int tx = tid & 15;        /* n group */
    const int ty = tid >> 4;        /* m group */

    float acc[8][8];
#pragma unroll
    for (int i = 0; i < 8; i++)
#pragma unroll
        for (int j = 0; j < 8; j++) acc[i][j] = 0.f;

    for (int k0 = 0; k0 < K; k0 += 16) {
#pragma unroll
        for (int i = 0; i < 8; i++) {           /* A tile: 128 rows x 16 cols */
            int idx = tid + i * 256;
            int r = idx >> 4, c = idx & 15;
            int gm = m0 + r, gk = k0 + c;
            As[c][r] = (gm < M && gk < K) ? A[(long long)gm * K + gk] : 0.f;
        }
#pragma unroll
        for (int i = 0; i < 8; i++) {           /* B tile: 16 rows x 128 cols */
            int idx = tid + i * 256;
            int r = idx >> 7, c = idx & 127;
            int gk = k0 + r, gn = n0 + c;
            Bs[r][c] = (gk < K && gn < N) ? B[(long long)gk * N + gn] : 0.f;
        }
        __syncthreads();
#pragma unroll
        for (int k = 0; k < 16; k++) {
            float4 a0 = *(const float4*)&As[k][ty * 8];
            float4 a1 = *(const float4*)&As[k][ty * 8 + 4];
            float4 b0 = *(const float4*)&Bs[k][tx * 8];
            float4 b1 = *(const float4*)&Bs[k][tx * 8 + 4];
            float a[8] = {a0.x,a0.y,a0.z,a0.w,a1.x,a1.y,a1.z,a1.w};
            float b[8] = {b0.x,b0.y,b0.z,b0.w,b1.x,b1.y,b1.z,b1.w};
#pragma unroll
            for (int i = 0; i < 8; i++)
#pragma unroll
                for (int j = 0; j < 8; j++)
                    acc[i][j] = fmaf(a[i], b[j], acc[i][j]);
        }
        __syncthreads();
    }

#pragma unroll
    for (int i = 0; i < 8; i++) {
        int gm = m0 + ty * 8 + i;
        if (gm >= M) break;
#pragma unroll
        for (int j = 0; j < 8; j++) {
            int gn = n0 + tx * 8 + j;
            if (gn < N) {
                float v = alpha * acc[i][j];
                if (bias) v += bias[gn];
                if (ACT)  v = v > 0.f ? v : 0.01f * v;    /* leaky relu 0.01 */
                long long off = (long long)gm * N + gn;
                C[off] = beta ? (C[off] + v) : v;
            }
        }
    }
}

/* ------------------------ DFT matrix tables (cos/sin), recomputed per call */
__global__ void dft_init_kernel()
{
    long long idx = (long long)blockIdx.x * blockDim.x + threadIdx.x;
    const float TWO_PI = 6.283185307179586f;
    if (idx < (long long)NTOK * NTOK) {
        int m = (int)(idx / NTOK), j = (int)(idx % NTOK);
        int r = (int)(((long long)m * j) % NTOK);
        float a = (float)r * (TWO_PI / (float)NTOK);
        float s, c; sincosf(a, &s, &c);
        g_CM[idx] = c; g_SM[idx] = s;
    }
    if (idx < (long long)Dd * Dd) {
        int n = (int)(idx / Dd), k = (int)(idx % Dd);
        int r = (n * k) & (Dd - 1);
        float a = (float)r * (TWO_PI / (float)Dd);
        float s, c; sincosf(a, &s, &c);
        g_CN[idx] = c; g_SN[idx] = s;
    }
}

/* ------------------------ im2col for kernel==stride conv */
__global__ void im2col_kernel(const float* __restrict__ x)
{
    long long idx = (long long)blockIdx.x * blockDim.x + threadIdx.x;
    if (idx >= (long long)Bsz * NPp * KIN) return;
    int k  = (int)(idx % KIN);
    long long rp = idx / KIN;
    int p  = (int)(rp % NPp);
    int b  = (int)(rp / NPp);
    int c  = k >> 8;
    int py = (k >> 4) & 15;
    int px = k & 15;
    int gh = p >> 5, gw = p & 31;
    g_col[idx] = x[(((long long)b * Cc + c) * Hh + gh * Pp + py) * Ww + gw * Pp + px];
}

__global__ void wmat_kernel(const float* __restrict__ cw)
{
    int idx = blockIdx.x * blockDim.x + threadIdx.x;
    if (idx >= KIN * Dd) return;
    int k = idx / Dd, d = idx % Dd;
    g_wmat[idx] = cw[(long long)d * KIN + k];
}

/* t[b,0,:] = cls + pos[0]; t[b,s,:] += pos[s] for s>=1 (conv_b already added by GEMM) */
__global__ void finish_tok_kernel(const float* __restrict__ pos, const float* __restrict__ cls)
{
    int d = threadIdx.x, s = blockIdx.x, b = blockIdx.y;
    long long off = ((long long)b * NTOK + s) * Dd + d;
    float p = pos[s * Dd + d];
    if (s == 0) g_t[off] = cls[d] + p;
    else        g_t[off] += p;
}

/* ------------------------ row LayerNorm over Dd=256, one block per row */
__global__ void ln_kernel(const float* __restrict__ x, float* __restrict__ y,
                          const float* __restrict__ sc, const float* __restrict__ bi)
{
    int row = blockIdx.x, tid = threadIdx.x;
    int lane = tid & 31, wid = tid >> 5;
    __shared__ float wred[8];
    __shared__ float sval;
    float v = x[(long long)row * Dd + tid];
    float s = v;
#pragma unroll
    for (int o = 16; o; o >>= 1) s += __shfl_xor_sync(0xffffffffu, s, o);
    if (!lane) wred[wid] = s;
    __syncthreads();
    if (!tid) { float a = 0; for (int i = 0; i < 8; i++) a += wred[i]; sval = a * (1.f / Dd); }
    __syncthreads();
    float m = sval, d = v - m;
    s = d * d;
#pragma unroll
    for (int o = 16; o; o >>= 1) s += __shfl_xor_sync(0xffffffffu, s, o);
    if (!lane) wred[wid] = s;
    __syncthreads();
    if (!tid) { float a = 0; for (int i = 0; i < 8; i++) a += wred[i]; sval = rsqrtf(a * (1.f / Dd) + EPSV); }
    __syncthreads();
    y[(long long)row * Dd + tid] = d * sval * sc[tid] + bi[tid];
}

/* ------------------------ mean pool over tokens */
__global__ void pool_kernel()
{
    int b = blockIdx.x, d = threadIdx.x;
    float s = 0.f;
    const float* base = g_t + (long long)b * NTOK * Dd + d;
    for (int p = 0; p < NTOK; p++) s += base[(long long)p * Dd];
    g_pool[b * Dd + d] = s * (1.f / (float)NTOK);
}

/* ------------------------ head: LN -> matmul(256x1000) -> softmax, one block per batch */
__global__ void head_kernel(const float* __restrict__ hs, const float* __restrict__ hbv,
                            const float* __restrict__ W, const float* __restrict__ hbias,
                            float* __restrict__ out)
{
    int b = blockIdx.x, tid = threadIdx.x;
    int lane = tid & 31, wid = tid >> 5;
    __shared__ float row[Dd];
    __shared__ float logits[NCls];
    __shared__ float wred[8];
    __shared__ float sval;

    float v = g_pool[b * Dd + tid];
    float s = v;
#pragma unroll
    for (int o = 16; o; o >>= 1) s += __shfl_xor_sync(0xffffffffu, s, o);
    if (!lane) wred[wid] = s;
    __syncthreads();
    if (!tid) { float a = 0; for (int i = 0; i < 8; i++) a += wred[i]; sval = a * (1.f / Dd); }
    __syncthreads();
    float m = sval, d = v - m;
    s = d * d;
#pragma unroll
    for (int o = 16; o; o >>= 1) s += __shfl_xor_sync(0xffffffffu, s, o);
    if (!lane) wred[wid] = s;
    __syncthreads();
    if (!tid) { float a = 0; for (int i = 0; i < 8; i++) a += wred[i]; sval = rsqrtf(a * (1.f / Dd) + EPSV); }
    __syncthreads();
    row[tid] = d * sval * hs[tid] + hbv[tid];
    __syncthreads();

    for (int n = tid; n < NCls; n += 256) {
        float acc = hbias[n];
        for (int k = 0; k < Dd; k++)
            acc = fmaf(row[k], W[(long long)k * NCls + n], acc);
        logits[n] = acc;
    }
    __syncthreads();

    float mx = -1e30f;
    for (int n = tid; n < NCls; n += 256) mx = fmaxf(mx, logits[n]);
#pragma unroll
    for (int o = 16; o; o >>= 1) mx = fmaxf(mx, __shfl_xor_sync(0xffffffffu, mx, o));
    if (!lane) wred[wid] = mx;
    __syncthreads();
    if (!tid) { float a = -1e30f; for (int i = 0; i < 8; i++) a = fmaxf(a, wred[i]); sval = a; }
    __syncthreads();
    mx = sval;
    float ls = 0.f;
    for (int n = tid; n < NCls; n += 256) {
        float e = expf(logits[n] - mx);
        logits[n] = e;
        ls += e;
    }
#pragma unroll
    for (int o = 16; o; o >>= 1) ls += __shfl_xor_sync(0xffffffffu, ls, o);
    if (!lane) wred[wid] = ls;
    __syncthreads();
    if (!tid) { float a = 0; for (int i = 0; i < 8; i++) a += wred[i]; sval = 1.f / a; }
    __syncthreads();
    float inv = sval;
    for (int n = tid; n < NCls; n += 256)
        out[(long long)b * NCls + n] = logits[n] * inv;
}

/* ------------------------ host-side GEMM dispatch */
static void gemm(const float* A, const float* B, float* C, int M, int N, int K,
                 long long sA, long long sB, long long sC, int batch,
                 float alpha, int beta, const float* bias, int act)
{
    dim3 grid((N + 127) / 128, (M + 127) / 128, batch), blk(256);
    if (act) sgemm<1><<<grid, blk>>>(A, B, C, M, N, K, sA, sB, sC, alpha, beta, bias);
    else     sgemm<0><<<grid, blk>>>(A, B, C, M, N, K, sA, sB, sC, alpha, beta, bias);
}

extern "C" void kernel_launch(void* const* d_in, const int* in_sizes, int n_in,
                              void* d_out, int out_size)
{
    const float* x      = (const float*)d_in[0];
    const float* conv_w = (const float*)d_in[1];
    const float* conv_b = (const float*)d_in[2];
    const float* pos    = (const float*)d_in[3];
    const float* cls    = (const float*)d_in[4];
    const float* ln1s   = (const float*)d_in[5];
    const float* ln1b   = (const float*)d_in[6];
    const float* ln2s   = (const float*)d_in[7];
    const float* ln2b   = (const float*)d_in[8];
    const float* w1     = (const float*)d_in[9];
    const float* b1     = (const float*)d_in[10];
    const float* w2     = (const float*)d_in[11];
    const float* b2     = (const float*)d_in[12];
    const float* hlns   = (const float*)d_in[13];
    const float* hlnb   = (const float*)d_in[14];
    const float* hw     = (const float*)d_in[15];
    const float* hb     = (const float*)d_in[16];
    float* out = (float*)d_out;

    float *t, *h, *t1, *t2, *hid, *col, *wm, *CM, *SM, *CN, *SN;
    cudaGetSymbolAddress((void**)&t,   g_t);
    cudaGetSymbolAddress((void**)&h,   g_h);
    cudaGetSymbolAddress((void**)&t1,  g_tmp1);
    cudaGetSymbolAddress((void**)&t2,  g_tmp2);
    cudaGetSymbolAddress((void**)&hid, g_hid);
    cudaGetSymbolAddress((void**)&col, g_col);
    cudaGetSymbolAddress((void**)&wm,  g_wmat);
    cudaGetSymbolAddress((void**)&CM,  g_CM);
    cudaGetSymbolAddress((void**)&SM,  g_SM);
    cudaGetSymbolAddress((void**)&CN,  g_CN);
    cudaGetSymbolAddress((void**)&SN,  g_SN);

    /* DFT tables (must be recomputed every call: no caching allowed) */
    {
        long long n = (long long)NTOK * NTOK;
        dft_init_kernel<<<(unsigned)((n + 255) / 256), 256>>>();
    }

    /* patch embed: im2col + batched GEMM into t[b,1:,:] with conv bias */
    {
        long long n = (long long)Bsz * NPp * KIN;
        im2col_kernel<<<(unsigned)((n + 255) / 256), 256>>>(x);
        wmat_kernel<<<(KIN * Dd + 255) / 256, 256>>>(conv_w);
        gemm(col, wm, t + Dd, NPp, Dd, KIN,
             (long long)NPp * KIN, 0, (long long)NTOK * Dd, Bsz,
             1.f, 0, conv_b, 0);
        finish_tok_kernel<<<dim3(NTOK, Bsz), Dd>>>(pos, cls);
    }

    const long long sBT = (long long)NTOK * Dd;   /* per-batch token-matrix stride */

    for (int i = 0; i < NL; i++) {
        /* ---- token mixing: t += CM @ (LN1(t) @ CN) - SM @ (LN1(t) @ SN) ---- */
        ln_kernel<<<ROWS, Dd>>>(t, h, ln1s + i * Dd, ln1b + i * Dd);
        gemm(h, CN, t1, ROWS, Dd, Dd, 0, 0, 0, 1, 1.f, 0, nullptr, 0);
        gemm(h, SN, t2, ROWS, Dd, Dd, 0, 0, 0, 1, 1.f, 0, nullptr, 0);
        gemm(CM, t1, t, NTOK, Dd, NTOK, 0, sBT, sBT, Bsz,  1.f, 1, nullptr, 0);
        gemm(SM, t2, t, NTOK, Dd, NTOK, 0, sBT, sBT, Bsz, -1.f, 1, nullptr, 0);

        /* ---- FFN: t += leaky(LN2(t) @ w1 + b1) @ w2 + b2 ---- */
        ln_kernel<<<ROWS, Dd>>>(t, h, ln2s + i * Dd, ln2b + i * Dd);
        gemm(h, w1 + (long long)i * Dd * HIDN, hid, ROWS, HIDN, Dd,
             0, 0, 0, 1, 1.f, 0, b1 + i * HIDN, 1);
        gemm(hid, w2 + (long long)i * HIDN * Dd, t, ROWS, Dd, HIDN,
             0, 0, 0, 1, 1.f, 1, b2 + i * Dd, 0);
    }

    pool_kernel<<<Bsz, Dd>>>();
    head_kernel<<<Bsz, Dd>>>(hlns, hlnb, hw, hb, out);
}